// round 3
// baseline (speedup 1.0000x reference)
#include <cuda_runtime.h>
#include <cuda_bf16.h>
#include <math.h>

// Problem constants
#define BB 2
#define TT 2048
#define DD 2048
#define HH 16
#define HD 128
#define LAT 512
#define RD 64
#define CD 64
#define MTOT (BB*TT)            // 4096
#define QSCALE 0.08838834764831845f  // 1/sqrt(128)
#define LOG10000 9.210340371976184f

// ---------------- scratch buffers (no cudaMalloc allowed) ----------------
// g_qproj doubles as the attention-output buffer: build_q_kernel fully consumes
// it before flash_attn_kernel writes the same region (strict stream order).
__device__ float g_qproj[MTOT * 2048];   // (B*T, H*HD) qproj -> later attn out
__device__ float g_kv   [MTOT * 1024];   // (B*T, 2*LAT)
__device__ float g_kr   [MTOT * 64];     // (B*T, RD)
__device__ float g_kc   [MTOT * 1024];   // (B*T, H*CD)
__device__ float g_vproj[MTOT * 2048];   // (B*T, H*HD)  == V in (b,t,h,d)
__device__ float g_q    [BB*HH*TT*HD];   // (B,H,T,HD) pre-scaled, rope applied
__device__ float g_k    [BB*HH*TT*HD];   // (B,H,T,HD)

// ---------------- generic SGEMM: C[M,N] = A[M,K](lda) * Bw[N,K]^T + bias ----------------
__global__ __launch_bounds__(256) void sgemm_nt_bias(
    const float* __restrict__ A, int lda,
    const float* __restrict__ Bw,                  // [N,K] row-major (K-major)
    const float* __restrict__ bias,
    float* __restrict__ C, int ldc,
    int M, int N, int K)
{
    __shared__ float As[16][128];
    __shared__ float Bs[16][128];

    const int bm = blockIdx.y * 128;
    const int bn = blockIdx.x * 128;
    const int tid = threadIdx.x;
    const int ty = tid >> 4;       // 0..15
    const int tx = tid & 15;       // 0..15

    float acc[8][8];
#pragma unroll
    for (int i = 0; i < 8; ++i)
#pragma unroll
        for (int j = 0; j < 8; ++j) acc[i][j] = 0.f;

    for (int k0 = 0; k0 < K; k0 += 16) {
#pragma unroll
        for (int r = 0; r < 2; ++r) {
            int idx = tid + r * 256;       // 0..511 (float4 index)
            int row = idx >> 2;            // 0..127
            int c4  = (idx & 3) * 4;       // 0,4,8,12
            float4 av = *(const float4*)&A[(size_t)(bm + row) * lda + k0 + c4];
            As[c4+0][row] = av.x; As[c4+1][row] = av.y;
            As[c4+2][row] = av.z; As[c4+3][row] = av.w;
            float4 bv = make_float4(0.f, 0.f, 0.f, 0.f);
            if (bn + row < N)
                bv = *(const float4*)&Bw[(size_t)(bn + row) * K + k0 + c4];
            Bs[c4+0][row] = bv.x; Bs[c4+1][row] = bv.y;
            Bs[c4+2][row] = bv.z; Bs[c4+3][row] = bv.w;
        }
        __syncthreads();
#pragma unroll
        for (int kk = 0; kk < 16; ++kk) {
            float4 a0 = *(const float4*)&As[kk][ty * 8];
            float4 a1 = *(const float4*)&As[kk][ty * 8 + 4];
            float4 b0 = *(const float4*)&Bs[kk][tx * 8];
            float4 b1 = *(const float4*)&Bs[kk][tx * 8 + 4];
            float ar[8] = {a0.x,a0.y,a0.z,a0.w,a1.x,a1.y,a1.z,a1.w};
            float br[8] = {b0.x,b0.y,b0.z,b0.w,b1.x,b1.y,b1.z,b1.w};
#pragma unroll
            for (int i = 0; i < 8; ++i)
#pragma unroll
                for (int j = 0; j < 8; ++j)
                    acc[i][j] = fmaf(ar[i], br[j], acc[i][j]);
        }
        __syncthreads();
    }

#pragma unroll
    for (int i = 0; i < 8; ++i) {
        int row = bm + ty * 8 + i;
#pragma unroll
        for (int j = 0; j < 8; j += 4) {
            int col = bn + tx * 8 + j;
            if (col < N) {
                float4 v;
                v.x = acc[i][j+0] + bias[col+0];
                v.y = acc[i][j+1] + bias[col+1];
                v.z = acc[i][j+2] + bias[col+2];
                v.w = acc[i][j+3] + bias[col+3];
                *(float4*)&C[(size_t)row * ldc + col] = v;
            }
        }
    }
}

// ---------------- RoPE helper ----------------
__device__ __forceinline__ void rope_cs(int t, int i, float& c, float& s) {
    // inv_freq = 10000^{-i/32}
    float inv = expf(-(float)i * (LOG10000 / 32.0f));
    float ang = (float)t * inv;
    sincosf(ang, &s, &c);
}

// ---------------- build q: (B*T, H*HD) -> (B,H,T,HD), rope on tail RD, pre-scale ----------------
__global__ __launch_bounds__(256) void build_q_kernel() {
    int idx = blockIdx.x * 256 + threadIdx.x;      // output index in (b,h,t,d)
    int d = idx & 127;
    int t = (idx >> 7) & 2047;
    int h = (idx >> 18) & 15;
    int b = idx >> 22;
    const float* src = g_qproj + ((size_t)(b * 2048 + t)) * 2048 + h * 128;
    float val;
    if (d < CD) {
        val = src[d];
    } else {
        int i = d - CD;             // 0..63
        float c, s;
        if (i < 32) {
            rope_cs(t, i, c, s);
            val = src[d] * c - src[d + 32] * s;
        } else {
            rope_cs(t, i - 32, c, s);
            val = src[d] * c + src[d - 32] * s;
        }
    }
    g_q[idx] = val * QSCALE;
}

// ---------------- build k: content + shared rope key -> (B,H,T,HD) ----------------
__global__ __launch_bounds__(256) void build_k_kernel() {
    int idx = blockIdx.x * 256 + threadIdx.x;
    int d = idx & 127;
    int t = (idx >> 7) & 2047;
    int h = (idx >> 18) & 15;
    int b = idx >> 22;
    float val;
    if (d < CD) {
        val = g_kc[((size_t)(b * 2048 + t)) * 1024 + h * 64 + d];
    } else {
        const float* kr = g_kr + ((size_t)(b * 2048 + t)) * 64;
        int i = d - CD;             // 0..63
        float c, s;
        if (i < 32) {
            rope_cs(t, i, c, s);
            val = kr[i] * c - kr[i + 32] * s;
        } else {
            rope_cs(t, i - 32, c, s);
            val = kr[i] * c + kr[i - 32] * s;
        }
    }
    g_k[idx] = val;
}

// ---------------- flash attention, fp32, causal, BM=BN=64, HD=128 ----------------
// Q,K in (B,H,T,HD).  V read strided from g_vproj (B*T, H*HD).
// O written strided into g_qproj (reused as (B*T, H*HD) attention output).
// smem: Qs[128][64] (d-major), Ks[128][64] (d-major), Vs[64][128], Ps[64][68]
#define FA_SMEM_FLOATS (8192 + 8192 + 8192 + 64 * 68)

__global__ __launch_bounds__(256) void flash_attn_kernel()
{
    extern __shared__ float sm[];
    float* Qs = sm;
    float* Ks = sm + 8192;
    float* Vs = sm + 16384;
    float* Ps = sm + 24576;

    const int qb = blockIdx.x * 64;
    const int bh = blockIdx.y;                 // 0..B*H-1
    const int b = bh >> 4;
    const int h = bh & 15;
    const float* Qp = g_q + ((size_t)bh * 2048 + qb) * 128;
    const float* Kp = g_k + (size_t)bh * 2048 * 128;
    // V: row t of this (b,h) lives at g_vproj[(b*2048+t)*2048 + h*128], stride 2048
    const float* Vp = g_vproj + ((size_t)b * 2048) * 2048 + h * 128;
    float* Op = g_qproj + ((size_t)(b * 2048 + qb)) * 2048 + h * 128;

    const int tid = threadIdx.x;
    const int ti = tid >> 4;                   // 0..15 : row group (4 rows)
    const int tj = tid & 15;                   // 0..15 : col group

    // load Q tile transposed (d-major)
#pragma unroll
    for (int r = 0; r < 8; ++r) {
        int idx = tid + r * 256;               // float4 index 0..2047
        int row = idx >> 5;                    // 0..63
        int c = (idx & 31) * 4;                // 0..124
        float4 v = *(const float4*)&Qp[row * 128 + c];
        Qs[(c+0)*64 + row] = v.x; Qs[(c+1)*64 + row] = v.y;
        Qs[(c+2)*64 + row] = v.z; Qs[(c+3)*64 + row] = v.w;
    }

    float m[4], l[4], o[4][8];
#pragma unroll
    for (int a = 0; a < 4; ++a) {
        m[a] = -1e30f; l[a] = 0.f;
#pragma unroll
        for (int c = 0; c < 8; ++c) o[a][c] = 0.f;
    }

    const int ntiles = (qb >> 6) + 1;
    for (int kt = 0; kt < ntiles; ++kt) {
        __syncthreads();                       // protect Ks/Vs/Ps reuse
        const float* Kt = Kp + (size_t)kt * 64 * 128;
        const float* Vt = Vp + (size_t)kt * 64 * 2048;
#pragma unroll
        for (int r = 0; r < 8; ++r) {
            int idx = tid + r * 256;
            int row = idx >> 5;
            int c = (idx & 31) * 4;
            float4 kv = *(const float4*)&Kt[row * 128 + c];
            Ks[(c+0)*64 + row] = kv.x; Ks[(c+1)*64 + row] = kv.y;
            Ks[(c+2)*64 + row] = kv.z; Ks[(c+3)*64 + row] = kv.w;
            *(float4*)&Vs[row * 128 + c] = *(const float4*)&Vt[(size_t)row * 2048 + c];
        }
        __syncthreads();

        // S = Q K^T  (q pre-scaled by 1/sqrt(HD))
        float s[4][4];
#pragma unroll
        for (int a = 0; a < 4; ++a)
#pragma unroll
            for (int c = 0; c < 4; ++c) s[a][c] = 0.f;

#pragma unroll 8
        for (int d = 0; d < 128; ++d) {
            float4 q = *(const float4*)&Qs[d * 64 + ti * 4];
            float4 k = *(const float4*)&Ks[d * 64 + tj * 4];
            s[0][0] = fmaf(q.x, k.x, s[0][0]); s[0][1] = fmaf(q.x, k.y, s[0][1]);
            s[0][2] = fmaf(q.x, k.z, s[0][2]); s[0][3] = fmaf(q.x, k.w, s[0][3]);
            s[1][0] = fmaf(q.y, k.x, s[1][0]); s[1][1] = fmaf(q.y, k.y, s[1][1]);
            s[1][2] = fmaf(q.y, k.z, s[1][2]); s[1][3] = fmaf(q.y, k.w, s[1][3]);
            s[2][0] = fmaf(q.z, k.x, s[2][0]); s[2][1] = fmaf(q.z, k.y, s[2][1]);
            s[2][2] = fmaf(q.z, k.z, s[2][2]); s[2][3] = fmaf(q.z, k.w, s[2][3]);
            s[3][0] = fmaf(q.w, k.x, s[3][0]); s[3][1] = fmaf(q.w, k.y, s[3][1]);
            s[3][2] = fmaf(q.w, k.z, s[3][2]); s[3][3] = fmaf(q.w, k.w, s[3][3]);
        }

        // causal mask only on diagonal tile
        if (kt == ntiles - 1) {
#pragma unroll
            for (int a = 0; a < 4; ++a)
#pragma unroll
                for (int c = 0; c < 4; ++c)
                    if (kt * 64 + tj * 4 + c > qb + ti * 4 + a) s[a][c] = -1e30f;
        }

        // online softmax update (16-lane row groups)
#pragma unroll
        for (int a = 0; a < 4; ++a) {
            float mx = fmaxf(fmaxf(s[a][0], s[a][1]), fmaxf(s[a][2], s[a][3]));
            mx = fmaxf(mx, __shfl_xor_sync(0xffffffffu, mx, 1, 16));
            mx = fmaxf(mx, __shfl_xor_sync(0xffffffffu, mx, 2, 16));
            mx = fmaxf(mx, __shfl_xor_sync(0xffffffffu, mx, 4, 16));
            mx = fmaxf(mx, __shfl_xor_sync(0xffffffffu, mx, 8, 16));
            float mn = fmaxf(m[a], mx);
            float sf = __expf(m[a] - mn);
            float p0 = __expf(s[a][0] - mn);
            float p1 = __expf(s[a][1] - mn);
            float p2 = __expf(s[a][2] - mn);
            float p3 = __expf(s[a][3] - mn);
            float ls = p0 + p1 + p2 + p3;
            ls += __shfl_xor_sync(0xffffffffu, ls, 1, 16);
            ls += __shfl_xor_sync(0xffffffffu, ls, 2, 16);
            ls += __shfl_xor_sync(0xffffffffu, ls, 4, 16);
            ls += __shfl_xor_sync(0xffffffffu, ls, 8, 16);
            l[a] = l[a] * sf + ls;
            m[a] = mn;
#pragma unroll
            for (int c = 0; c < 8; ++c) o[a][c] *= sf;
            *(float4*)&Ps[(ti * 4 + a) * 68 + tj * 4] = make_float4(p0, p1, p2, p3);
        }
        __syncthreads();

        // O += P V
#pragma unroll 4
        for (int j = 0; j < 64; ++j) {
            float4 v0 = *(const float4*)&Vs[j * 128 + tj * 8];
            float4 v1 = *(const float4*)&Vs[j * 128 + tj * 8 + 4];
#pragma unroll
            for (int a = 0; a < 4; ++a) {
                float p = Ps[(ti * 4 + a) * 68 + j];
                o[a][0] = fmaf(p, v0.x, o[a][0]); o[a][1] = fmaf(p, v0.y, o[a][1]);
                o[a][2] = fmaf(p, v0.z, o[a][2]); o[a][3] = fmaf(p, v0.w, o[a][3]);
                o[a][4] = fmaf(p, v1.x, o[a][4]); o[a][5] = fmaf(p, v1.y, o[a][5]);
                o[a][6] = fmaf(p, v1.z, o[a][6]); o[a][7] = fmaf(p, v1.w, o[a][7]);
            }
        }
    }

    // epilogue: normalize + strided store into (B*T, H*HD)
#pragma unroll
    for (int a = 0; a < 4; ++a) {
        float inv = 1.0f / l[a];
        float4 r0 = make_float4(o[a][0]*inv, o[a][1]*inv, o[a][2]*inv, o[a][3]*inv);
        float4 r1 = make_float4(o[a][4]*inv, o[a][5]*inv, o[a][6]*inv, o[a][7]*inv);
        float* orow = Op + (size_t)(ti * 4 + a) * 2048;
        *(float4*)&orow[tj * 8]     = r0;
        *(float4*)&orow[tj * 8 + 4] = r1;
    }
}

// ---------------- launch ----------------
extern "C" void kernel_launch(void* const* d_in, const int* in_sizes, int n_in,
                              void* d_out, int out_size)
{
    const float* x   = (const float*)d_in[0];
    const float* Wq  = (const float*)d_in[1];
    const float* bq  = (const float*)d_in[2];
    const float* Wkv = (const float*)d_in[3];
    const float* bkv = (const float*)d_in[4];
    const float* Wkr = (const float*)d_in[5];
    const float* bkr = (const float*)d_in[6];
    const float* Wku = (const float*)d_in[7];
    const float* bku = (const float*)d_in[8];
    const float* Wvu = (const float*)d_in[9];
    const float* bvu = (const float*)d_in[10];
    const float* Wo  = (const float*)d_in[11];
    const float* bo  = (const float*)d_in[12];
    float* out = (float*)d_out;

    // one-time symbol-address lookup + smem opt-in (deterministic, capture-safe)
    static float *qproj = nullptr, *kv, *kr, *kc, *vproj;
    if (!qproj) {
        cudaGetSymbolAddress((void**)&qproj, g_qproj);
        cudaGetSymbolAddress((void**)&kv,    g_kv);
        cudaGetSymbolAddress((void**)&kr,    g_kr);
        cudaGetSymbolAddress((void**)&kc,    g_kc);
        cudaGetSymbolAddress((void**)&vproj, g_vproj);
        cudaFuncSetAttribute(flash_attn_kernel,
                             cudaFuncAttributeMaxDynamicSharedMemorySize,
                             FA_SMEM_FLOATS * sizeof(float));
    }

    const int M = MTOT;
    dim3 thr(256);

    // projections from x
    sgemm_nt_bias<<<dim3(2048/128, M/128), thr>>>(x, DD, Wq,  bq,  qproj, 2048, M, 2048, 2048);
    sgemm_nt_bias<<<dim3(1024/128, M/128), thr>>>(x, DD, Wkv, bkv, kv,    1024, M, 1024, 2048);
    sgemm_nt_bias<<<dim3(1,        M/128), thr>>>(x, DD, Wkr, bkr, kr,      64, M,   64, 2048);
    // up-projections from latents (kv split: first 512 = k latent, next 512 = v latent)
    sgemm_nt_bias<<<dim3(1024/128, M/128), thr>>>(kv,       1024, Wku, bku, kc,    1024, M, 1024, 512);
    sgemm_nt_bias<<<dim3(2048/128, M/128), thr>>>(kv + 512, 1024, Wvu, bvu, vproj, 2048, M, 2048, 512);

    // layout builds + rope (fully consume qproj before attention reuses it)
    int nelem = BB * HH * TT * HD;           // 2^23
    build_q_kernel<<<nelem / 256, thr>>>();
    build_k_kernel<<<nelem / 256, thr>>>();

    // attention (V read from vproj, O written into qproj buffer, both strided)
    flash_attn_kernel<<<dim3(TT / 64, BB * HH), thr, FA_SMEM_FLOATS * sizeof(float)>>>();

    // output projection
    sgemm_nt_bias<<<dim3(2048/128, M/128), thr>>>(qproj, 2048, Wo, bo, out, 2048, M, 2048, 2048);
}

// round 4
// speedup vs baseline: 1.6962x; 1.6962x over previous
#include <cuda_runtime.h>
#include <cuda_bf16.h>
#include <math.h>
#include <stdint.h>

// Problem constants
#define BB 2
#define TT 2048
#define DD 2048
#define HH 16
#define HD 128
#define LAT 512
#define RD 64
#define CD 64
#define MTOT (BB*TT)            // 4096
#define QSCALE 0.08838834764831845f  // 1/sqrt(128)
#define LOG10000 9.210340371976184f

// ---------------- scratch buffers (no cudaMalloc allowed) ----------------
// g_qproj doubles as the attention-output buffer: build_q_kernel fully consumes
// it before flash_attn_kernel writes the same region (strict stream order).
__device__ float g_qproj[MTOT * 2048];   // (B*T, H*HD) qproj -> later attn out
__device__ float g_kv   [MTOT * 1024];   // (B*T, 2*LAT)
__device__ float g_kr   [MTOT * 64];     // (B*T, RD)
__device__ float g_kc   [MTOT * 1024];   // (B*T, H*CD)
__device__ float g_vproj[MTOT * 2048];   // (B*T, H*HD)  == V in (b,t,h,d)
__device__ float g_q    [BB*HH*TT*HD];   // (B,H,T,HD) pre-scaled, rope applied
__device__ float g_k    [BB*HH*TT*HD];   // (B,H,T,HD)

// ---------------- bf16x3 tensor-core GEMM ----------------
// C[M,N] = A[M,K](row, lda) * Bw[N,K]^T + bias, fp32 in/out.
// fp32 operands split to bf16 hi/lo during smem staging; 3 HMMA terms
// (ah*bh + ah*bl + al*bh) with fp32 accumulate => ~1e-5 relative accuracy.
// CTA tile 128x128x32, 8 warps (4m x 2n), warp tile 32x64.

__device__ __forceinline__ uint32_t smem_u32(const void* p) {
    return (uint32_t)__cvta_generic_to_shared(p);
}

__device__ __forceinline__ void ldsm_x4(uint32_t* r, uint32_t addr) {
    asm volatile("ldmatrix.sync.aligned.m8n8.x4.shared.b16 {%0,%1,%2,%3}, [%4];\n"
        : "=r"(r[0]), "=r"(r[1]), "=r"(r[2]), "=r"(r[3]) : "r"(addr));
}

__device__ __forceinline__ void mma16816(float* c, const uint32_t* a, uint32_t b0, uint32_t b1) {
    asm volatile(
        "mma.sync.aligned.m16n8k16.row.col.f32.bf16.bf16.f32 "
        "{%0,%1,%2,%3}, {%4,%5,%6,%7}, {%8,%9}, {%0,%1,%2,%3};\n"
        : "+f"(c[0]), "+f"(c[1]), "+f"(c[2]), "+f"(c[3])
        : "r"(a[0]), "r"(a[1]), "r"(a[2]), "r"(a[3]), "r"(b0), "r"(b1));
}

__device__ __forceinline__ void split2(float x, float y, uint32_t& hi, uint32_t& lo) {
    __nv_bfloat16 hx = __float2bfloat16_rn(x);
    __nv_bfloat16 hy = __float2bfloat16_rn(y);
    __nv_bfloat16 lx = __float2bfloat16_rn(x - __bfloat162float(hx));
    __nv_bfloat16 ly = __float2bfloat16_rn(y - __bfloat162float(hy));
    hi = ((uint32_t)__bfloat16_as_ushort(hy) << 16) | (uint32_t)__bfloat16_as_ushort(hx);
    lo = ((uint32_t)__bfloat16_as_ushort(ly) << 16) | (uint32_t)__bfloat16_as_ushort(lx);
}

#define GPITCH 20   // 32-bit words per smem row (=40 bf16); conflict-free for ldmatrix

__global__ __launch_bounds__(256, 2) void bf16x3_gemm_nt_bias(
    const float* __restrict__ A, int lda,
    const float* __restrict__ Bw,                  // [N,K] row-major (K-major)
    const float* __restrict__ bias,
    float* __restrict__ C, int ldc,
    int M, int N, int K)
{
    __shared__ uint32_t Ah[128 * GPITCH], Al[128 * GPITCH];
    __shared__ uint32_t Bh[128 * GPITCH], Bl[128 * GPITCH];

    const int tid = threadIdx.x;
    const int bm = blockIdx.y * 128;
    const int bn = blockIdx.x * 128;
    const int wid = tid >> 5, lane = tid & 31;
    const int wm = wid & 3;           // 0..3 (m warp)
    const int wn = wid >> 2;          // 0..1 (n warp)
    const int groupID = lane >> 2, tig = lane & 3;
    const int lrow = lane & 15;               // ldmatrix row within 16-row tile
    const int lkw  = (lane >> 4) * 4;         // ldmatrix word offset (k+0 / k+8)

    float c[2][8][4];
#pragma unroll
    for (int mt = 0; mt < 2; ++mt)
#pragma unroll
        for (int nt = 0; nt < 8; ++nt)
#pragma unroll
            for (int r = 0; r < 4; ++r) c[mt][nt][r] = 0.f;

    for (int k0 = 0; k0 < K; k0 += 32) {
        __syncthreads();
        // stage A (128 x 32 fp32 -> hi/lo bf16), 4 float4 per thread
#pragma unroll
        for (int i = 0; i < 4; ++i) {
            int idx = tid + i * 256;
            int row = idx >> 3;
            int cw = (idx & 7) * 2;            // word col 0,2,..,14
            float4 v = *(const float4*)&A[(size_t)(bm + row) * lda + k0 + cw * 2];
            uint32_t h0, l0, h1, l1;
            split2(v.x, v.y, h0, l0);
            split2(v.z, v.w, h1, l1);
            Ah[row * GPITCH + cw] = h0; Ah[row * GPITCH + cw + 1] = h1;
            Al[row * GPITCH + cw] = l0; Al[row * GPITCH + cw + 1] = l1;
        }
        // stage B with N guard
#pragma unroll
        for (int i = 0; i < 4; ++i) {
            int idx = tid + i * 256;
            int row = idx >> 3;
            int cw = (idx & 7) * 2;
            float4 v = make_float4(0.f, 0.f, 0.f, 0.f);
            if (bn + row < N)
                v = *(const float4*)&Bw[(size_t)(bn + row) * K + k0 + cw * 2];
            uint32_t h0, l0, h1, l1;
            split2(v.x, v.y, h0, l0);
            split2(v.z, v.w, h1, l1);
            Bh[row * GPITCH + cw] = h0; Bh[row * GPITCH + cw + 1] = h1;
            Bl[row * GPITCH + cw] = l0; Bl[row * GPITCH + cw + 1] = l1;
        }
        __syncthreads();

#pragma unroll
        for (int kk = 0; kk < 2; ++kk) {
            uint32_t ah[2][4], al[2][4];
#pragma unroll
            for (int mt = 0; mt < 2; ++mt) {
                int arow = wm * 32 + mt * 16 + lrow;
                uint32_t aaddr = smem_u32(&Ah[arow * GPITCH + kk * 8 + lkw]);
                uint32_t laddr = smem_u32(&Al[arow * GPITCH + kk * 8 + lkw]);
                ldsm_x4(ah[mt], aaddr);
                ldsm_x4(al[mt], laddr);
            }
#pragma unroll
            for (int nt2 = 0; nt2 < 4; ++nt2) {
                int brow = wn * 64 + nt2 * 16 + lrow;
                uint32_t bh[4], bl[4];
                ldsm_x4(bh, smem_u32(&Bh[brow * GPITCH + kk * 8 + lkw]));
                ldsm_x4(bl, smem_u32(&Bl[brow * GPITCH + kk * 8 + lkw]));
#pragma unroll
                for (int s = 0; s < 2; ++s) {
#pragma unroll
                    for (int mt = 0; mt < 2; ++mt) {
                        float* acc = c[mt][nt2 * 2 + s];
                        mma16816(acc, ah[mt], bh[s], bh[s + 2]);
                        mma16816(acc, ah[mt], bl[s], bl[s + 2]);
                        mma16816(acc, al[mt], bh[s], bh[s + 2]);
                    }
                }
            }
        }
    }

    // epilogue: bias + store
#pragma unroll
    for (int mt = 0; mt < 2; ++mt) {
        int row = bm + wm * 32 + mt * 16 + groupID;
#pragma unroll
        for (int nt = 0; nt < 8; ++nt) {
            int col = bn + wn * 64 + nt * 8 + tig * 2;
            if (col < N) {
                float b0 = bias[col], b1 = bias[col + 1];
                float2 v0 = make_float2(c[mt][nt][0] + b0, c[mt][nt][1] + b1);
                float2 v1 = make_float2(c[mt][nt][2] + b0, c[mt][nt][3] + b1);
                *(float2*)&C[(size_t)row * ldc + col] = v0;
                *(float2*)&C[(size_t)(row + 8) * ldc + col] = v1;
            }
        }
    }
}

// ---------------- RoPE helper ----------------
__device__ __forceinline__ void rope_cs(int t, int i, float& c, float& s) {
    float inv = expf(-(float)i * (LOG10000 / 32.0f));
    float ang = (float)t * inv;
    sincosf(ang, &s, &c);
}

// ---------------- build q: (B*T, H*HD) -> (B,H,T,HD), rope on tail RD, pre-scale ----------------
__global__ __launch_bounds__(256) void build_q_kernel() {
    int idx = blockIdx.x * 256 + threadIdx.x;
    int d = idx & 127;
    int t = (idx >> 7) & 2047;
    int h = (idx >> 18) & 15;
    int b = idx >> 22;
    const float* src = g_qproj + ((size_t)(b * 2048 + t)) * 2048 + h * 128;
    float val;
    if (d < CD) {
        val = src[d];
    } else {
        int i = d - CD;
        float c, s;
        if (i < 32) {
            rope_cs(t, i, c, s);
            val = src[d] * c - src[d + 32] * s;
        } else {
            rope_cs(t, i - 32, c, s);
            val = src[d] * c + src[d - 32] * s;
        }
    }
    g_q[idx] = val * QSCALE;
}

// ---------------- build k: content + shared rope key -> (B,H,T,HD) ----------------
__global__ __launch_bounds__(256) void build_k_kernel() {
    int idx = blockIdx.x * 256 + threadIdx.x;
    int d = idx & 127;
    int t = (idx >> 7) & 2047;
    int h = (idx >> 18) & 15;
    int b = idx >> 22;
    float val;
    if (d < CD) {
        val = g_kc[((size_t)(b * 2048 + t)) * 1024 + h * 64 + d];
    } else {
        const float* kr = g_kr + ((size_t)(b * 2048 + t)) * 64;
        int i = d - CD;
        float c, s;
        if (i < 32) {
            rope_cs(t, i, c, s);
            val = kr[i] * c - kr[i + 32] * s;
        } else {
            rope_cs(t, i - 32, c, s);
            val = kr[i] * c + kr[i - 32] * s;
        }
    }
    g_k[idx] = val;
}

// ---------------- flash attention, fp32, causal, BM=BN=64, HD=128 ----------------
#define FA_SMEM_FLOATS (8192 + 8192 + 8192 + 64 * 68)

__global__ __launch_bounds__(256) void flash_attn_kernel()
{
    extern __shared__ float sm[];
    float* Qs = sm;
    float* Ks = sm + 8192;
    float* Vs = sm + 16384;
    float* Ps = sm + 24576;

    const int qb = blockIdx.x * 64;
    const int bh = blockIdx.y;
    const int b = bh >> 4;
    const int h = bh & 15;
    const float* Qp = g_q + ((size_t)bh * 2048 + qb) * 128;
    const float* Kp = g_k + (size_t)bh * 2048 * 128;
    const float* Vp = g_vproj + ((size_t)b * 2048) * 2048 + h * 128;
    float* Op = g_qproj + ((size_t)(b * 2048 + qb)) * 2048 + h * 128;

    const int tid = threadIdx.x;
    const int ti = tid >> 4;
    const int tj = tid & 15;

#pragma unroll
    for (int r = 0; r < 8; ++r) {
        int idx = tid + r * 256;
        int row = idx >> 5;
        int c = (idx & 31) * 4;
        float4 v = *(const float4*)&Qp[row * 128 + c];
        Qs[(c+0)*64 + row] = v.x; Qs[(c+1)*64 + row] = v.y;
        Qs[(c+2)*64 + row] = v.z; Qs[(c+3)*64 + row] = v.w;
    }

    float m[4], l[4], o[4][8];
#pragma unroll
    for (int a = 0; a < 4; ++a) {
        m[a] = -1e30f; l[a] = 0.f;
#pragma unroll
        for (int c = 0; c < 8; ++c) o[a][c] = 0.f;
    }

    const int ntiles = (qb >> 6) + 1;
    for (int kt = 0; kt < ntiles; ++kt) {
        __syncthreads();
        const float* Kt = Kp + (size_t)kt * 64 * 128;
        const float* Vt = Vp + (size_t)kt * 64 * 2048;
#pragma unroll
        for (int r = 0; r < 8; ++r) {
            int idx = tid + r * 256;
            int row = idx >> 5;
            int c = (idx & 31) * 4;
            float4 kv = *(const float4*)&Kt[row * 128 + c];
            Ks[(c+0)*64 + row] = kv.x; Ks[(c+1)*64 + row] = kv.y;
            Ks[(c+2)*64 + row] = kv.z; Ks[(c+3)*64 + row] = kv.w;
            *(float4*)&Vs[row * 128 + c] = *(const float4*)&Vt[(size_t)row * 2048 + c];
        }
        __syncthreads();

        float s[4][4];
#pragma unroll
        for (int a = 0; a < 4; ++a)
#pragma unroll
            for (int c = 0; c < 4; ++c) s[a][c] = 0.f;

#pragma unroll 8
        for (int d = 0; d < 128; ++d) {
            float4 q = *(const float4*)&Qs[d * 64 + ti * 4];
            float4 k = *(const float4*)&Ks[d * 64 + tj * 4];
            s[0][0] = fmaf(q.x, k.x, s[0][0]); s[0][1] = fmaf(q.x, k.y, s[0][1]);
            s[0][2] = fmaf(q.x, k.z, s[0][2]); s[0][3] = fmaf(q.x, k.w, s[0][3]);
            s[1][0] = fmaf(q.y, k.x, s[1][0]); s[1][1] = fmaf(q.y, k.y, s[1][1]);
            s[1][2] = fmaf(q.y, k.z, s[1][2]); s[1][3] = fmaf(q.y, k.w, s[1][3]);
            s[2][0] = fmaf(q.z, k.x, s[2][0]); s[2][1] = fmaf(q.z, k.y, s[2][1]);
            s[2][2] = fmaf(q.z, k.z, s[2][2]); s[2][3] = fmaf(q.z, k.w, s[2][3]);
            s[3][0] = fmaf(q.w, k.x, s[3][0]); s[3][1] = fmaf(q.w, k.y, s[3][1]);
            s[3][2] = fmaf(q.w, k.z, s[3][2]); s[3][3] = fmaf(q.w, k.w, s[3][3]);
        }

        if (kt == ntiles - 1) {
#pragma unroll
            for (int a = 0; a < 4; ++a)
#pragma unroll
                for (int c = 0; c < 4; ++c)
                    if (kt * 64 + tj * 4 + c > qb + ti * 4 + a) s[a][c] = -1e30f;
        }

#pragma unroll
        for (int a = 0; a < 4; ++a) {
            float mx = fmaxf(fmaxf(s[a][0], s[a][1]), fmaxf(s[a][2], s[a][3]));
            mx = fmaxf(mx, __shfl_xor_sync(0xffffffffu, mx, 1, 16));
            mx = fmaxf(mx, __shfl_xor_sync(0xffffffffu, mx, 2, 16));
            mx = fmaxf(mx, __shfl_xor_sync(0xffffffffu, mx, 4, 16));
            mx = fmaxf(mx, __shfl_xor_sync(0xffffffffu, mx, 8, 16));
            float mn = fmaxf(m[a], mx);
            float sf = __expf(m[a] - mn);
            float p0 = __expf(s[a][0] - mn);
            float p1 = __expf(s[a][1] - mn);
            float p2 = __expf(s[a][2] - mn);
            float p3 = __expf(s[a][3] - mn);
            float ls = p0 + p1 + p2 + p3;
            ls += __shfl_xor_sync(0xffffffffu, ls, 1, 16);
            ls += __shfl_xor_sync(0xffffffffu, ls, 2, 16);
            ls += __shfl_xor_sync(0xffffffffu, ls, 4, 16);
            ls += __shfl_xor_sync(0xffffffffu, ls, 8, 16);
            l[a] = l[a] * sf + ls;
            m[a] = mn;
#pragma unroll
            for (int c = 0; c < 8; ++c) o[a][c] *= sf;
            *(float4*)&Ps[(ti * 4 + a) * 68 + tj * 4] = make_float4(p0, p1, p2, p3);
        }
        __syncthreads();

#pragma unroll 4
        for (int j = 0; j < 64; ++j) {
            float4 v0 = *(const float4*)&Vs[j * 128 + tj * 8];
            float4 v1 = *(const float4*)&Vs[j * 128 + tj * 8 + 4];
#pragma unroll
            for (int a = 0; a < 4; ++a) {
                float p = Ps[(ti * 4 + a) * 68 + j];
                o[a][0] = fmaf(p, v0.x, o[a][0]); o[a][1] = fmaf(p, v0.y, o[a][1]);
                o[a][2] = fmaf(p, v0.z, o[a][2]); o[a][3] = fmaf(p, v0.w, o[a][3]);
                o[a][4] = fmaf(p, v1.x, o[a][4]); o[a][5] = fmaf(p, v1.y, o[a][5]);
                o[a][6] = fmaf(p, v1.z, o[a][6]); o[a][7] = fmaf(p, v1.w, o[a][7]);
            }
        }
    }

#pragma unroll
    for (int a = 0; a < 4; ++a) {
        float inv = 1.0f / l[a];
        float4 r0 = make_float4(o[a][0]*inv, o[a][1]*inv, o[a][2]*inv, o[a][3]*inv);
        float4 r1 = make_float4(o[a][4]*inv, o[a][5]*inv, o[a][6]*inv, o[a][7]*inv);
        float* orow = Op + (size_t)(ti * 4 + a) * 2048;
        *(float4*)&orow[tj * 8]     = r0;
        *(float4*)&orow[tj * 8 + 4] = r1;
    }
}

// ---------------- launch ----------------
extern "C" void kernel_launch(void* const* d_in, const int* in_sizes, int n_in,
                              void* d_out, int out_size)
{
    const float* x   = (const float*)d_in[0];
    const float* Wq  = (const float*)d_in[1];
    const float* bq  = (const float*)d_in[2];
    const float* Wkv = (const float*)d_in[3];
    const float* bkv = (const float*)d_in[4];
    const float* Wkr = (const float*)d_in[5];
    const float* bkr = (const float*)d_in[6];
    const float* Wku = (const float*)d_in[7];
    const float* bku = (const float*)d_in[8];
    const float* Wvu = (const float*)d_in[9];
    const float* bvu = (const float*)d_in[10];
    const float* Wo  = (const float*)d_in[11];
    const float* bo  = (const float*)d_in[12];
    float* out = (float*)d_out;

    static float *qproj = nullptr, *kv, *kr, *kc, *vproj;
    if (!qproj) {
        cudaGetSymbolAddress((void**)&qproj, g_qproj);
        cudaGetSymbolAddress((void**)&kv,    g_kv);
        cudaGetSymbolAddress((void**)&kr,    g_kr);
        cudaGetSymbolAddress((void**)&kc,    g_kc);
        cudaGetSymbolAddress((void**)&vproj, g_vproj);
        cudaFuncSetAttribute(flash_attn_kernel,
                             cudaFuncAttributeMaxDynamicSharedMemorySize,
                             FA_SMEM_FLOATS * sizeof(float));
    }

    const int M = MTOT;
    dim3 thr(256);

    // projections from x (tensor-core bf16x3)
    bf16x3_gemm_nt_bias<<<dim3(16, 32), thr>>>(x, DD, Wq,  bq,  qproj, 2048, M, 2048, 2048);
    bf16x3_gemm_nt_bias<<<dim3(8,  32), thr>>>(x, DD, Wkv, bkv, kv,    1024, M, 1024, 2048);
    bf16x3_gemm_nt_bias<<<dim3(1,  32), thr>>>(x, DD, Wkr, bkr, kr,      64, M,   64, 2048);
    // up-projections from latents
    bf16x3_gemm_nt_bias<<<dim3(8,  32), thr>>>(kv,       1024, Wku, bku, kc,    1024, M, 1024, 512);
    bf16x3_gemm_nt_bias<<<dim3(16, 32), thr>>>(kv + 512, 1024, Wvu, bvu, vproj, 2048, M, 2048, 512);

    // layout builds + rope (fully consume qproj before attention reuses it)
    int nelem = BB * HH * TT * HD;
    build_q_kernel<<<nelem / 256, thr>>>();
    build_k_kernel<<<nelem / 256, thr>>>();

    // attention (V read from vproj, O written into qproj buffer, both strided)
    flash_attn_kernel<<<dim3(TT / 64, BB * HH), thr, FA_SMEM_FLOATS * sizeof(float)>>>();

    // output projection
    bf16x3_gemm_nt_bias<<<dim3(16, 32), thr>>>(qproj, 2048, Wo, bo, out, 2048, M, 2048, 2048);
}